// round 4
// baseline (speedup 1.0000x reference)
#include <cuda_runtime.h>
#include <math.h>

#define EPSF 1e-12f
#define KFIX 64
#define NSLOT 65                 // slot 0: below-linear, 1..63: intervals, 64: above-linear
#define S_TILE 32
#define THREADS 256
#define BCHUNKS 8
#define TILE_F4 (NSLOT * S_TILE) // 2080 float4

static __device__ __forceinline__ float sgnf(float v) {
    return (float)((v > 0.f) - (v < 0.f));
}

// PCHIP slope at knot k for one spline row, from shared y / knots.
static __device__ __forceinline__ float d_of(const float* __restrict__ yr,
                                             const float* __restrict__ sk, int k) {
    if (k == 0) {
        float h0 = sk[1] - sk[0], h1 = sk[2] - sk[1];
        float del0 = (yr[1] - yr[0]) / (h0 + EPSF);
        float del1 = (yr[2] - yr[1]) / (h1 + EPSF);
        float d0 = ((2.f * h0 + h1) * del0 - h0 * del1) / (h0 + h1 + EPSF);
        if (sgnf(d0) != sgnf(del0)) d0 = 0.f;
        if ((sgnf(del0) != sgnf(del1)) && (fabsf(d0) > 3.f * fabsf(del0))) d0 = 3.f * del0;
        return d0;
    } else if (k == KFIX - 1) {
        float hn1 = sk[KFIX - 1] - sk[KFIX - 2], hn2 = sk[KFIX - 2] - sk[KFIX - 3];
        float deln1 = (yr[KFIX - 1] - yr[KFIX - 2]) / (hn1 + EPSF);
        float deln2 = (yr[KFIX - 2] - yr[KFIX - 3]) / (hn2 + EPSF);
        float dn = ((2.f * hn1 + hn2) * deln1 - hn1 * deln2) / (hn1 + hn2 + EPSF);
        if (sgnf(dn) != sgnf(deln1)) dn = 0.f;
        if ((sgnf(deln1) != sgnf(deln2)) && (fabsf(dn) > 3.f * fabsf(deln1))) dn = 3.f * deln1;
        return dn;
    } else {
        float hp = sk[k] - sk[k - 1], hn = sk[k + 1] - sk[k];
        float dp = (yr[k] - yr[k - 1]) / (hp + EPSF);
        float dnx = (yr[k + 1] - yr[k]) / (hn + EPSF);
        float w1 = 2.f * hn + hp;
        float w2 = hn + 2.f * hp;
        float denom = w1 / (dp + EPSF) + w2 / (dnx + EPSF);
        float di = (w1 + w2) / (denom + EPSF);
        return (dp * dnx > 0.f) ? di : 0.f;
    }
}

// Fused: block = (s-tile of 32 splines) x (chunk of ~512 b-rows).
// Phase 1 builds the 65-slot monomial table for its splines in smem,
// Phase 2 streams xq -> out with one clamp + one LDS.128 gather + Horner.
__global__ __launch_bounds__(THREADS) void pchip_fused_kernel(
    const float* __restrict__ xq, const float* __restrict__ coeffs,
    const float* __restrict__ knots, float* __restrict__ out, int B, int S) {

    __shared__ float4 stile[TILE_F4];         // 33280 B, layout [slot*32 + row]
    __shared__ float sy[S_TILE][KFIX + 1];    // 8320 B (stride 65: conflict-free both ways)
    __shared__ float sk[KFIX];

    const int tid = threadIdx.x;
    const int s0 = blockIdx.x * S_TILE;

    // ---- Phase 1a: load knots + this tile's y values (coalesced) ----
    if (tid < KFIX) sk[tid] = knots[tid];
    #pragma unroll
    for (int i = tid; i < S_TILE * KFIX; i += THREADS) {
        int row = i >> 6, k = i & 63;
        int s = s0 + row;
        sy[row][k] = (s < S) ? coeffs[(size_t)s * KFIX + k] : 0.f;
    }
    __syncthreads();

    // ---- Phase 1b: monomial coefficients. Mapping: k = i>>5 (per warp),
    // row = i&31 (per lane) -> STS to consecutive float4 (conflict-free). ----
    const float hk = (sk[KFIX - 1] - sk[0]) * (1.f / (float)(KFIX - 1));
    #pragma unroll
    for (int i = tid; i < S_TILE * KFIX; i += THREADS) {
        int k = i >> 5, row = i & 31;
        const float* yr = sy[row];
        if (k < KFIX - 1) {
            float d0 = d_of(yr, sk, k);
            float d1 = d_of(yr, sk, k + 1);
            float h = sk[k + 1] - sk[k] + EPSF;     // reference adds EPS in eval
            float y0 = yr[k], y1 = yr[k + 1];
            float dy = y1 - y0;
            float4 c;
            c.x = y0;
            c.y = h * d0;
            c.z = 3.f * dy - h * (2.f * d0 + d1);
            c.w = -2.f * dy + h * (d0 + d1);
            stile[((k + 1) << 5) + row] = c;
            if (k == 0) {
                // slot 0: below-domain linear in t = u+1
                float g = hk * d0;
                stile[row] = make_float4(y0 - g, g, 0.f, 0.f);
            }
        } else { // k == 63: slot 64, above-domain linear in t = u-63
            float dn = d_of(yr, sk, KFIX - 1);
            stile[((NSLOT - 1) << 5) + row] =
                make_float4(yr[KFIX - 1], hk * dn, 0.f, 0.f);
        }
    }
    __syncthreads();

    // ---- Phase 2: streaming eval ----
    const float k0 = sk[0];
    const float inv_h = (float)(KFIX - 1) / (sk[KFIX - 1] - k0);
    const float off0 = 1.f - k0 * inv_h;          // u1 = x*inv_h + off0 = u+1

    const int sl = tid & 31;
    const int s = s0 + sl;
    if (s >= S) return;
    const float4* base = stile + sl;

    const int chunk = (B + BCHUNKS - 1) / BCHUNKS;
    const int b0 = blockIdx.y * chunk;
    const int bmax = min(chunk, B - b0);
    const int bl0 = tid >> 5;

    #pragma unroll 4
    for (int bl = bl0; bl < bmax; bl += 8) {
        size_t off = (size_t)(b0 + bl) * S + s;
        float x = __ldcs(xq + off);
        float u1 = fmaf(x, inv_h, off0);
        float uc = fminf(fmaxf(u1, 0.5f), 64.5f);  // slot in [0, 64]
        int slot = __float2int_rd(uc);
        float t = u1 - (float)slot;
        float4 c = base[slot << 5];
        __stcs(out + off, fmaf(t, fmaf(t, fmaf(t, c.w, c.z), c.y), c.x));
    }
}

extern "C" void kernel_launch(void* const* d_in, const int* in_sizes, int n_in,
                              void* d_out, int out_size) {
    const float* xq = (const float*)d_in[0];
    const float* coeffs = (const float*)d_in[1];
    const float* knots = (const float*)d_in[2];
    float* out = (float*)d_out;

    int K = in_sizes[2];          // 64
    int S = in_sizes[1] / K;      // 4096
    int B = in_sizes[0] / S;      // 4096

    dim3 grid((S + S_TILE - 1) / S_TILE, BCHUNKS);
    pchip_fused_kernel<<<grid, THREADS>>>(xq, coeffs, knots, out, B, S);
}

// round 5
// speedup vs baseline: 1.9317x; 1.9317x over previous
#include <cuda_runtime.h>
#include <math.h>

#define EPSF 1e-12f
#define KFIX 64
#define NSLOT 65                 // slot 0: below-linear, 1..63: intervals, 64: above-linear
#define S_TILE 32
#define TILE_F4 (NSLOT * S_TILE) // 2080 float4 per 32-spline tile

#define ETHREADS 512
#define B_TILE 256

// Monomial coefficients, transposed per 32-spline tile:
//   g_C[(s>>5)*2080 + slot*32 + (s&31)]
__device__ float4 g_C[(4096 / S_TILE) * TILE_F4];

static __device__ __forceinline__ float sgnf(float v) {
    return (float)((v > 0.f) - (v < 0.f));
}
static __device__ __forceinline__ float fdiv(float a, float b) {
    return __fdividef(a, b);
}

// One block per 32-spline tile. 256 threads. All work in smem, fast divides,
// coalesced 512B/warp stores into the transposed g_C tile.
__global__ __launch_bounds__(256) void pchip_coeff_kernel(
    const float* __restrict__ coeffs, const float* __restrict__ knots, int S) {
    __shared__ float sk[KFIX];
    __shared__ float sy[S_TILE][KFIX + 1];    // stride 65 -> conflict-free both axes
    __shared__ float sdel[S_TILE][KFIX + 1];
    __shared__ float sd[S_TILE][KFIX + 1];

    const int tid = threadIdx.x;
    const int s0 = blockIdx.x * S_TILE;

    if (tid < KFIX) sk[tid] = knots[tid];
    #pragma unroll
    for (int i = tid; i < S_TILE * KFIX; i += 256) {
        int row = i >> 6, k = i & 63;
        int s = s0 + row;
        sy[row][k] = (s < S) ? coeffs[(size_t)s * KFIX + k] : 0.f;
    }
    __syncthreads();

    // deltas: mapping k = i>>5 (warp), row = i&31 (lane): stride-65 conflict-free
    #pragma unroll
    for (int i = tid; i < S_TILE * KFIX; i += 256) {
        int k = i >> 5, row = i & 31;
        if (k < KFIX - 1) {
            float h = sk[k + 1] - sk[k];
            sdel[row][k] = fdiv(sy[row][k + 1] - sy[row][k], h + EPSF);
        }
    }
    __syncthreads();

    // PCHIP slopes
    #pragma unroll
    for (int i = tid; i < S_TILE * KFIX; i += 256) {
        int k = i >> 5, row = i & 31;
        float d;
        if (k == 0) {
            float h0 = sk[1] - sk[0], h1 = sk[2] - sk[1];
            float del0 = sdel[row][0], del1 = sdel[row][1];
            float d0 = fdiv((2.f * h0 + h1) * del0 - h0 * del1, h0 + h1 + EPSF);
            if (sgnf(d0) != sgnf(del0)) d0 = 0.f;
            if ((sgnf(del0) != sgnf(del1)) && (fabsf(d0) > 3.f * fabsf(del0))) d0 = 3.f * del0;
            d = d0;
        } else if (k == KFIX - 1) {
            float hn1 = sk[KFIX - 1] - sk[KFIX - 2], hn2 = sk[KFIX - 2] - sk[KFIX - 3];
            float deln1 = sdel[row][KFIX - 2], deln2 = sdel[row][KFIX - 3];
            float dn = fdiv((2.f * hn1 + hn2) * deln1 - hn1 * deln2, hn1 + hn2 + EPSF);
            if (sgnf(dn) != sgnf(deln1)) dn = 0.f;
            if ((sgnf(deln1) != sgnf(deln2)) && (fabsf(dn) > 3.f * fabsf(deln1))) dn = 3.f * deln1;
            d = dn;
        } else {
            float dp = sdel[row][k - 1], dnx = sdel[row][k];
            float hp = sk[k] - sk[k - 1], hn = sk[k + 1] - sk[k];
            float w1 = 2.f * hn + hp;
            float w2 = hn + 2.f * hp;
            float denom = fdiv(w1, dp + EPSF) + fdiv(w2, dnx + EPSF);
            float di = fdiv(w1 + w2, denom + EPSF);
            d = (dp * dnx > 0.f) ? di : 0.f;
        }
        sd[row][k] = d;
    }
    __syncthreads();

    // Monomial coefficients; warp k stores 32 consecutive float4 (coalesced).
    const float hk = (sk[KFIX - 1] - sk[0]) * (1.f / (float)(KFIX - 1));
    float4* tb = g_C + (size_t)blockIdx.x * TILE_F4;
    #pragma unroll
    for (int i = tid; i < S_TILE * KFIX; i += 256) {
        int k = i >> 5, row = i & 31;
        if (k < KFIX - 1) {
            float h = sk[k + 1] - sk[k] + EPSF;      // reference adds EPS in eval
            float y0 = sy[row][k], y1 = sy[row][k + 1];
            float d0 = sd[row][k], d1 = sd[row][k + 1];
            float dy = y1 - y0;
            float4 c;
            c.x = y0;
            c.y = h * d0;
            c.z = 3.f * dy - h * (2.f * d0 + d1);
            c.w = -2.f * dy + h * (d0 + d1);
            tb[((k + 1) << 5) + row] = c;
            if (k == 0) {                            // slot 0: below-domain linear (t = u+1)
                float g = hk * d0;
                tb[row] = make_float4(y0 - g, g, 0.f, 0.f);
            }
        } else {                                     // slot 64: above-domain linear (t = u-63)
            tb[((NSLOT - 1) << 5) + row] =
                make_float4(sy[row][KFIX - 1], hk * sd[row][KFIX - 1], 0.f, 0.f);
        }
    }
}

// Eval: 512 threads = 16 b-rows x 32 s-lanes; each block covers 256 b x 32 s.
// 4 blocks/SM x 16 warps = 64 warps (100% occupancy). Gather layout
// stile[slot*32 + sl]: bank pattern independent of slot -> conflict-free LDS.128.
__global__ __launch_bounds__(ETHREADS) void pchip_eval_kernel(
    const float* __restrict__ xq, const float* __restrict__ knots,
    float* __restrict__ out, int B, int S) {
    __shared__ float4 stile[TILE_F4];   // 33.3 KB

    const int tid = threadIdx.x;
    const int s0 = blockIdx.x * S_TILE;
    const int b0 = blockIdx.y * B_TILE;

    const float4* Cbase = g_C + (size_t)blockIdx.x * TILE_F4;
    #pragma unroll
    for (int i = tid; i < TILE_F4; i += ETHREADS)
        stile[i] = Cbase[i];
    __syncthreads();

    const float k0 = __ldg(knots);
    const float inv_h = (float)(KFIX - 1) / (__ldg(knots + KFIX - 1) - k0);
    const float off0 = 1.f - k0 * inv_h;             // u1 = x*inv_h + off0 = u+1

    const int sl = tid & 31;
    const int s = s0 + sl;
    if (s >= S) return;
    const float4* base = stile + sl;
    const int bl0 = tid >> 5;                        // 0..15
    const int bmax = min(B_TILE, B - b0);

    #pragma unroll 4
    for (int bl = bl0; bl < bmax; bl += 16) {
        size_t off = (size_t)(b0 + bl) * S + s;
        float x = xq[off];
        float u1 = fmaf(x, inv_h, off0);
        float uc = fminf(fmaxf(u1, 0.5f), 64.5f);    // slot in [0, 64]
        int slot = __float2int_rd(uc);
        float t = u1 - (float)slot;
        float4 c = base[slot << 5];
        out[off] = fmaf(t, fmaf(t, fmaf(t, c.w, c.z), c.y), c.x);
    }
}

extern "C" void kernel_launch(void* const* d_in, const int* in_sizes, int n_in,
                              void* d_out, int out_size) {
    const float* xq = (const float*)d_in[0];
    const float* coeffs = (const float*)d_in[1];
    const float* knots = (const float*)d_in[2];
    float* out = (float*)d_out;

    int K = in_sizes[2];          // 64
    int S = in_sizes[1] / K;      // 4096
    int B = in_sizes[0] / S;      // 4096

    pchip_coeff_kernel<<<(S + S_TILE - 1) / S_TILE, 256>>>(coeffs, knots, S);

    dim3 grid((S + S_TILE - 1) / S_TILE, (B + B_TILE - 1) / B_TILE);
    pchip_eval_kernel<<<grid, ETHREADS>>>(xq, knots, out, B, S);
}

// round 7
// speedup vs baseline: 2.4082x; 1.2467x over previous
#include <cuda_runtime.h>
#include <math.h>

#define EPSF 1e-12f
#define KFIX 64
#define NSLOT 65                 // slot 0: below-linear, 1..63: intervals, 64: above-linear
#define S_TILE 32
#define TILE_F4 (NSLOT * S_TILE) // 2080 float4 per 32-spline tile

#define ETHREADS 512
#define B_TILE 256

// Monomial coefficients, transposed per 32-spline tile:
//   g_C[(s>>5)*2080 + slot*32 + (s&31)]
__device__ float4 g_C[(4096 / S_TILE) * TILE_F4];

static __device__ __forceinline__ float sgnf(float v) {
    return (float)((v > 0.f) - (v < 0.f));
}
static __device__ __forceinline__ float fdiv(float a, float b) {
    return __fdividef(a, b);
}

// One block per 32-spline tile, 1024 threads -> 2 (k,row) pairs per thread.
__global__ __launch_bounds__(1024) void pchip_coeff_kernel(
    const float* __restrict__ coeffs, const float* __restrict__ knots, int S) {
    __shared__ float sk[KFIX];
    __shared__ float sy[S_TILE][KFIX + 1];    // stride 65: conflict-free both axes
    __shared__ float sdel[S_TILE][KFIX + 1];
    __shared__ float sd[S_TILE][KFIX + 1];

    const int tid = threadIdx.x;
    const int s0 = blockIdx.x * S_TILE;

    if (tid < KFIX) sk[tid] = knots[tid];
    #pragma unroll
    for (int i = tid; i < S_TILE * KFIX; i += 1024) {
        int row = i >> 6, k = i & 63;
        int s = s0 + row;
        sy[row][k] = (s < S) ? coeffs[(size_t)s * KFIX + k] : 0.f;
    }
    __syncthreads();

    #pragma unroll
    for (int i = tid; i < S_TILE * KFIX; i += 1024) {
        int k = i >> 5, row = i & 31;
        if (k < KFIX - 1) {
            float h = sk[k + 1] - sk[k];
            sdel[row][k] = fdiv(sy[row][k + 1] - sy[row][k], h + EPSF);
        }
    }
    __syncthreads();

    #pragma unroll
    for (int i = tid; i < S_TILE * KFIX; i += 1024) {
        int k = i >> 5, row = i & 31;
        float d;
        if (k == 0) {
            float h0 = sk[1] - sk[0], h1 = sk[2] - sk[1];
            float del0 = sdel[row][0], del1 = sdel[row][1];
            float d0 = fdiv((2.f * h0 + h1) * del0 - h0 * del1, h0 + h1 + EPSF);
            if (sgnf(d0) != sgnf(del0)) d0 = 0.f;
            if ((sgnf(del0) != sgnf(del1)) && (fabsf(d0) > 3.f * fabsf(del0))) d0 = 3.f * del0;
            d = d0;
        } else if (k == KFIX - 1) {
            float hn1 = sk[KFIX - 1] - sk[KFIX - 2], hn2 = sk[KFIX - 2] - sk[KFIX - 3];
            float deln1 = sdel[row][KFIX - 2], deln2 = sdel[row][KFIX - 3];
            float dn = fdiv((2.f * hn1 + hn2) * deln1 - hn1 * deln2, hn1 + hn2 + EPSF);
            if (sgnf(dn) != sgnf(deln1)) dn = 0.f;
            if ((sgnf(deln1) != sgnf(deln2)) && (fabsf(dn) > 3.f * fabsf(deln1))) dn = 3.f * deln1;
            d = dn;
        } else {
            float dp = sdel[row][k - 1], dnx = sdel[row][k];
            float hp = sk[k] - sk[k - 1], hn = sk[k + 1] - sk[k];
            float w1 = 2.f * hn + hp;
            float w2 = hn + 2.f * hp;
            float denom = fdiv(w1, dp + EPSF) + fdiv(w2, dnx + EPSF);
            float di = fdiv(w1 + w2, denom + EPSF);
            d = (dp * dnx > 0.f) ? di : 0.f;
        }
        sd[row][k] = d;
    }
    __syncthreads();

    const float hk = (sk[KFIX - 1] - sk[0]) * (1.f / (float)(KFIX - 1));
    float4* tb = g_C + (size_t)blockIdx.x * TILE_F4;
    #pragma unroll
    for (int i = tid; i < S_TILE * KFIX; i += 1024) {
        int k = i >> 5, row = i & 31;
        if (k < KFIX - 1) {
            float h = sk[k + 1] - sk[k] + EPSF;      // reference adds EPS in eval
            float y0 = sy[row][k], y1 = sy[row][k + 1];
            float d0 = sd[row][k], d1 = sd[row][k + 1];
            float dy = y1 - y0;
            float4 c;
            c.x = y0;
            c.y = h * d0;
            c.z = 3.f * dy - h * (2.f * d0 + d1);
            c.w = -2.f * dy + h * (d0 + d1);
            tb[((k + 1) << 5) + row] = c;
            if (k == 0) {                            // slot 0: below-domain linear (t = u+1)
                float g = hk * d0;
                tb[row] = make_float4(y0 - g, g, 0.f, 0.f);
            }
        } else {                                     // slot 64: above-domain linear (t = u-63)
            tb[((NSLOT - 1) << 5) + row] =
                make_float4(sy[row][KFIX - 1], hk * sd[row][KFIX - 1], 0.f, 0.f);
        }
    }
}

// Eval: 512 threads = 16 b-rows x 32 s-lanes; block covers 256 b x 32 s.
// launch_bounds(512,3): ~40 regs so ptxas can batch 8 independent LDGs
// per loop body (explicit two half-batches below).
__global__ __launch_bounds__(ETHREADS, 3) void pchip_eval_kernel(
    const float* __restrict__ xq, const float* __restrict__ knots,
    float* __restrict__ out, int B, int S) {
    __shared__ float4 stile[TILE_F4];   // 33.3 KB

    const int tid = threadIdx.x;
    const int s0 = blockIdx.x * S_TILE;
    const int b0 = blockIdx.y * B_TILE;

    const float4* Cbase = g_C + (size_t)blockIdx.x * TILE_F4;
    #pragma unroll
    for (int i = tid; i < TILE_F4; i += ETHREADS)
        stile[i] = Cbase[i];
    __syncthreads();

    const float k0 = __ldg(knots);
    const float inv_h = (float)(KFIX - 1) / (__ldg(knots + KFIX - 1) - k0);
    const float offc = 1.f - k0 * inv_h;             // u1 = x*inv_h + offc = u+1

    const int sl = tid & 31;
    const int s = s0 + sl;
    if (s >= S) return;
    const float4* base = stile + sl;
    const int bl0 = tid >> 5;                        // 0..15
    const int bmax = min(B_TILE, B - b0);

    if (bmax == B_TILE) {
        // Fast path: 16 elements/thread in two explicit batches of 8.
        const size_t stride = (size_t)16 * S;
        size_t ofs = (size_t)(b0 + bl0) * S + s;
        #pragma unroll
        for (int half = 0; half < 2; half++) {
            float xs[8];
            #pragma unroll
            for (int j = 0; j < 8; j++)
                xs[j] = xq[ofs + (size_t)j * stride];
            #pragma unroll
            for (int j = 0; j < 8; j++) {
                float u1 = fmaf(xs[j], inv_h, offc);
                float uc = fminf(fmaxf(u1, 0.5f), 64.5f);   // slot in [0, 64]
                int slot = __float2int_rd(uc);
                float t = u1 - (float)slot;
                float4 c = base[slot << 5];
                out[ofs + (size_t)j * stride] =
                    fmaf(t, fmaf(t, fmaf(t, c.w, c.z), c.y), c.x);
            }
            ofs += 8 * stride;
        }
    } else {
        for (int bl = bl0; bl < bmax; bl += 16) {
            size_t off = (size_t)(b0 + bl) * S + s;
            float x = xq[off];
            float u1 = fmaf(x, inv_h, offc);
            float uc = fminf(fmaxf(u1, 0.5f), 64.5f);
            int slot = __float2int_rd(uc);
            float t = u1 - (float)slot;
            float4 c = base[slot << 5];
            out[off] = fmaf(t, fmaf(t, fmaf(t, c.w, c.z), c.y), c.x);
        }
    }
}

extern "C" void kernel_launch(void* const* d_in, const int* in_sizes, int n_in,
                              void* d_out, int out_size) {
    const float* xq = (const float*)d_in[0];
    const float* coeffs = (const float*)d_in[1];
    const float* knots = (const float*)d_in[2];
    float* out = (float*)d_out;

    int K = in_sizes[2];          // 64
    int S = in_sizes[1] / K;      // 4096
    int B = in_sizes[0] / S;      // 4096

    pchip_coeff_kernel<<<(S + S_TILE - 1) / S_TILE, 1024>>>(coeffs, knots, S);

    dim3 grid((S + S_TILE - 1) / S_TILE, (B + B_TILE - 1) / B_TILE);
    pchip_eval_kernel<<<grid, ETHREADS>>>(xq, knots, out, B, S);
}